// round 13
// baseline (speedup 1.0000x reference)
#include <cuda_runtime.h>
#include <cuda_bf16.h>
#include <cuda_fp16.h>
#include <math.h>
#include <stdint.h>

// Problem constants: B=4, L=1024, DM=768, DC=256, N=16, R=48, K=4, H=8, HD=32
// GEMMs + flash attention: single-pass fp16 operands, fp32 accumulate.

// ======================= scratch buffers (static; no allocation) =======================
__device__ float g_xc[4096 * 256];
__device__ float g_xdbl[4096 * 80];
__device__ float g_delta[4096 * 256];

__device__ __half g_xzyh[4096 * 768];
__device__ __half g_qkvh[4096 * 768];
__device__ __half g_hsS[4096 * 768];
__device__ __half g_winS[768 * 768];
__device__ __half g_xcS[4096 * 256];
__device__ __half g_wxpS[80 * 256];
__device__ __half g_dtS[4096 * 48];
__device__ __half g_wdtS[256 * 48];
__device__ __half g_ycS[4096 * 256];
__device__ __half g_wqkvS[768 * 256];
__device__ __half g_oS[4096 * 256];
__device__ __half g_watS[256 * 256];
__device__ __half g_catS[4096 * 768];
__device__ __half g_woutS[768 * 768];

// ======================= small asm helpers =======================
__device__ __forceinline__ uint32_t smem_to_u32(const void* smem_ptr) {
    uint32_t addr;
    asm("{ .reg .u64 tmp; cvta.to.shared.u64 tmp, %1; cvt.u32.u64 %0, tmp; }"
        : "=r"(addr) : "l"(smem_ptr));
    return addr;
}

__device__ __forceinline__ uint32_t lds32(uint32_t a) {
    uint32_t v;
    asm volatile("ld.shared.b32 %0, [%1];" : "=r"(v) : "r"(a));
    return v;
}

__device__ __forceinline__ void ldsm4(uint32_t* r, uint32_t a) {
    asm volatile("ldmatrix.sync.aligned.m8n8.x4.shared.b16 {%0,%1,%2,%3}, [%4];"
                 : "=r"(r[0]), "=r"(r[1]), "=r"(r[2]), "=r"(r[3]) : "r"(a));
}

__device__ __forceinline__ void cp16(uint32_t dst, const void* src, bool pred) {
    int sz = pred ? 16 : 0;
    asm volatile("cp.async.cg.shared.global [%0], [%1], 16, %2;"
                 :: "r"(dst), "l"(src), "r"(sz) : "memory");
}

__device__ __forceinline__ void mma_f16(float* c, const uint32_t* a, const uint32_t* b) {
    asm volatile(
        "mma.sync.aligned.m16n8k16.row.col.f32.f16.f16.f32 "
        "{%0,%1,%2,%3}, {%4,%5,%6,%7}, {%8,%9}, {%0,%1,%2,%3};"
        : "+f"(c[0]), "+f"(c[1]), "+f"(c[2]), "+f"(c[3])
        : "r"(a[0]), "r"(a[1]), "r"(a[2]), "r"(a[3]), "r"(b[0]), "r"(b[1]));
}

__device__ __forceinline__ uint32_t packf16(float x, float y) {
    __half2 t = __floats2half2_rn(x, y);
    return *(uint32_t*)&t;
}

// ======================= fp32 -> fp16 conversion =======================
__global__ void __launch_bounds__(256) half_kernel(
    const float* __restrict__ src, int ld,
    int M, int K, __half* __restrict__ dst)
{
    int idx = blockIdx.x * 256 + threadIdx.x;
    if (idx >= M * K) return;
    int m = idx / K, k = idx - m * K;
    dst[(long long)m * K + k] = __float2half_rn(src[(long long)m * ld + k]);
}

// ======================= merged weight conversions (ld==K contiguous) ==================
__global__ void __launch_bounds__(256) weight_half_kernel(
    const float* __restrict__ w_in, const float* __restrict__ w_xp,
    const float* __restrict__ w_dt, const float* __restrict__ w_qkv,
    const float* __restrict__ w_at, const float* __restrict__ w_out,
    __half* __restrict__ winS, __half* __restrict__ wxpS,
    __half* __restrict__ wdtS, __half* __restrict__ wqkvS,
    __half* __restrict__ watS, __half* __restrict__ woutS)
{
    int idx = blockIdx.x * 256 + threadIdx.x;
    const float* src; __half* dst;
    int rem = idx;
    if (rem < 589824)                 { src = w_in;  dst = winS;  }
    else if ((rem -= 589824) < 20480) { src = w_xp;  dst = wxpS;  }
    else if ((rem -= 20480) < 12288)  { src = w_dt;  dst = wdtS;  }
    else if ((rem -= 12288) < 196608) { src = w_qkv; dst = wqkvS; }
    else if ((rem -= 196608) < 65536) { src = w_at;  dst = watS;  }
    else                              { rem -= 65536; src = w_out; dst = woutS; }
    dst[rem] = __float2half_rn(src[rem]);
}

// ======================= HMMA fp16 NT GEMM, 128x64x32, 3-stage + ldmatrix ====================
// epi: 0 none, 1 +bias*bscale, 2 softplus(v + bias*bscale)
// ohalf: if 1, C is a __half buffer; write fp16 at coff+c (row stride ldc elements).
// dual: if splitx>0 and blockIdx.x>=splitx, switch to (A2,B2,C2,N2,ldc2), epi=0.
#define ASTR 80
#define STG 15360      // 128*80 (A) + 64*80 (B)
__global__ void __launch_bounds__(256, 3) gemm_mma(
    const __half* __restrict__ A, const __half* __restrict__ B,
    float* __restrict__ C, int M, int Nglob, int Kp,
    int lda, int ldb, int ldc, int coff,
    const float* __restrict__ bias, float bscale, float alpha, int epi,
    int ohalf,
    const __half* __restrict__ A2, const __half* __restrict__ B2,
    float* __restrict__ C2, int N2, int ldc2, int splitx)
{
    __shared__ __align__(16) char smem[3 * STG];
    uint32_t sb = smem_to_u32(smem);
    int tid = threadIdx.x;
    int bx = blockIdx.x;
    int n0;
    if (splitx && bx >= splitx) {
        A = A2; B = B2; C = C2; Nglob = N2; ldc = ldc2;
        epi = 0; ohalf = 0; coff = 0;
        n0 = (bx - splitx) * 64;
    } else {
        n0 = bx * 64;
    }
    int m0 = blockIdx.y * 128;
    int NC = (Kp + 31) >> 5;

    auto load_stage = [&](int c) {
        int k0 = c * 32;
        uint32_t ab = sb + (c % 3) * STG;
        uint32_t bb = ab + 10240;
        #pragma unroll
        for (int i = 0; i < 2; i++) {
            int gg = tid + i * 256;
            int r = gg >> 2, c16 = gg & 3;
            int k = k0 + c16 * 8;
            cp16(ab + r * ASTR + c16 * 16, A + (long long)(m0 + r) * lda + k, k < Kp);
        }
        {
            int r = tid >> 2, c16 = tid & 3;
            int k = k0 + c16 * 8;
            cp16(bb + r * ASTR + c16 * 16, B + (long long)(n0 + r) * ldb + k,
                 (n0 + r) < Nglob && k < Kp);
        }
        asm volatile("cp.async.commit_group;" ::: "memory");
    };

    int wid = tid >> 5, lane = tid & 31;
    int wm = wid & 3, wn = wid >> 2;          // 4x2 warps, warp tile 32x32
    int g = lane >> 2, tg = lane & 3;
    int l7 = lane & 7;

    uint32_t aoff0 = (uint32_t)((wm * 32 + l7 + ((lane >> 3) & 1) * 8) * ASTR + (lane >> 4) * 16);
    uint32_t aoff1 = aoff0 + 16 * ASTR;
    uint32_t boff0 = (uint32_t)((wn * 32 + (lane >> 4) * 8 + l7) * ASTR + ((lane >> 3) & 1) * 16);
    uint32_t boff1 = boff0 + 16 * ASTR;

    float acc[2][4][4] = {};

    load_stage(0);
    if (1 < NC) load_stage(1);

    for (int c = 0; c < NC; c++) {
        if (c + 1 < NC) { asm volatile("cp.async.wait_group 1;" ::: "memory"); }
        else            { asm volatile("cp.async.wait_group 0;" ::: "memory"); }
        __syncthreads();
        if (c + 2 < NC) load_stage(c + 2);

        uint32_t ab = sb + (c % 3) * STG;
        uint32_t bb = ab + 10240;
        #pragma unroll
        for (int ks = 0; ks < 2; ks++) {
            uint32_t a0[4], a1[4], b0[4], b1[4];
            ldsm4(a0, ab + aoff0 + ks * 32);
            ldsm4(a1, ab + aoff1 + ks * 32);
            ldsm4(b0, bb + boff0 + ks * 32);
            ldsm4(b1, bb + boff1 + ks * 32);
            mma_f16(acc[0][0], a0, b0 + 0);
            mma_f16(acc[0][1], a0, b0 + 2);
            mma_f16(acc[0][2], a0, b1 + 0);
            mma_f16(acc[0][3], a0, b1 + 2);
            mma_f16(acc[1][0], a1, b0 + 0);
            mma_f16(acc[1][1], a1, b0 + 2);
            mma_f16(acc[1][2], a1, b1 + 0);
            mma_f16(acc[1][3], a1, b1 + 2);
        }
    }
    __syncthreads();

    // ---- epilogue ----
    #pragma unroll
    for (int mi = 0; mi < 2; mi++) {
        int r0 = m0 + wm * 32 + mi * 16 + g;
        #pragma unroll
        for (int nj = 0; nj < 4; nj++) {
            int cc = n0 + wn * 32 + nj * 8 + tg * 2;
            if (cc >= Nglob) continue;
            #pragma unroll
            for (int hh = 0; hh < 2; hh++) {
                int rr = r0 + hh * 8;
                float v0 = acc[mi][nj][hh * 2 + 0] * alpha;
                float v1 = acc[mi][nj][hh * 2 + 1] * alpha;
                if (epi >= 1) { v0 += bias[cc] * bscale; v1 += bias[cc + 1] * bscale; }
                if (epi == 2) {
                    v0 = (v0 > 15.f) ? v0 : log1pf(__expf(v0));
                    v1 = (v1 > 15.f) ? v1 : log1pf(__expf(v1));
                }
                if (!ohalf) {
                    *(float2*)&C[(long long)rr * ldc + coff + cc] = make_float2(v0, v1);
                } else {
                    __half* Cb = (__half*)C;
                    long long base = (long long)rr * ldc + coff + cc;
                    *(__half2*)&Cb[base] = __floats2half2_rn(v0, v1);
                }
            }
        }
    }
}

// ======================= fused flash attention, fp16, Q-tile 64 =======================
// qkvh: fp16 (4096 x 768) [q|k|v]. Q tile 64 rows, K tiles 128 keys, HD=32.
// 8 warps: wm(4) x wn(2); warp = 16 M-rows x 64 keys.
#define FQK 80                    // 32 halfs (64B) + 16 pad
#define OFF_VT 10240              // V^T: 32 x 272
#define FSV 272
#define OFF_FRMAX 18944           // [2][64] floats
#define OFF_FRSUM 19456           // [2][64] floats
__global__ void __launch_bounds__(256) flash_kernel(
    const __half* __restrict__ qkvh, __half* __restrict__ oS)
{
    __shared__ __align__(16) char smem[20992];
    uint32_t sb = smem_to_u32(smem);
    float* rmax = (float*)(smem + OFF_FRMAX);
    float* rsum = (float*)(smem + OFF_FRSUM);
    int tid = threadIdx.x;
    int wid = tid >> 5, lane = tid & 31;
    int wm = wid & 3, wn = wid >> 2;
    int g = lane >> 2, tg = lane & 3;
    int z = blockIdx.y;
    int b = z >> 3, h = z & 7;
    int q0 = blockIdx.x * 64;
    const float alpha = 0.17677669529663687f;   // HD^-0.5
    const __half* qkvb = qkvh + (long long)b * 1024 * 768 + h * 32;

    // ---- stage Q (pre-scaled): 64 rows x 32 d ----
    #pragma unroll
    for (int j = 0; j < 8; j++) {
        int i = tid + j * 256;
        int row = i >> 5, d = i & 31;
        float f = __half2float(qkvb[(long long)(q0 + row) * 768 + d]) * alpha;
        *(__half*)(smem + row * FQK + d * 2) = __float2half_rn(f);
    }
    __syncthreads();
    // ---- Q A-frags to registers (persistent), warp rows wm*16..+16 ----
    uint32_t qa[2][4];
    #pragma unroll
    for (int kb = 0; kb < 2; kb++) {
        uint32_t base = sb + (wm * 16 + g) * FQK + kb * 32 + tg * 4;
        qa[kb][0] = lds32(base);
        qa[kb][1] = lds32(base + 8 * FQK);
        qa[kb][2] = lds32(base + 16);
        qa[kb][3] = lds32(base + 8 * FQK + 16);
    }

    float accO[4][4] = {};
    float m_run[2] = {-1e30f, -1e30f};
    float l_run[2] = {0.f, 0.f};

    for (int t = 0; t < 8; t++) {
        int j0 = t * 128;
        __syncthreads();
        // ---- K tile via cp.async (128 keys x 32 d) ----
        #pragma unroll
        for (int i = 0; i < 2; i++) {
            int gg = tid + i * 256;
            int r = gg >> 2, c16 = gg & 3;
            cp16(sb + r * FQK + c16 * 16,
                 qkvb + (long long)(j0 + r) * 768 + 256 + c16 * 8, true);
        }
        asm volatile("cp.async.commit_group;" ::: "memory");
        // ---- V^T scalar transpose copies ----
        #pragma unroll
        for (int j = 0; j < 16; j++) {
            int i = tid + j * 256;
            int key = i >> 5, d = i & 31;
            *(__half*)(smem + OFF_VT + d * FSV + key * 2) =
                qkvb[(long long)(j0 + key) * 768 + 512 + d];
        }
        asm volatile("cp.async.wait_group 0;" ::: "memory");
        __syncthreads();

        // ---- S = Q @ K^T (warp: 16 rows x 64 keys) ----
        float accS[8][4] = {};
        #pragma unroll
        for (int kb = 0; kb < 2; kb++) {
            uint32_t bfr[8][2];
            #pragma unroll
            for (int nj = 0; nj < 8; nj++) {
                uint32_t base = sb + (wn * 64 + nj * 8 + g) * FQK + kb * 32 + tg * 4;
                bfr[nj][0] = lds32(base);
                bfr[nj][1] = lds32(base + 16);
            }
            #pragma unroll
            for (int nj = 0; nj < 8; nj++)
                mma_f16(accS[nj], qa[kb], bfr[nj]);
        }

        // ---- online softmax ----
        float mx[2];
        #pragma unroll
        for (int hh = 0; hh < 2; hh++) {
            float m = -1e30f;
            #pragma unroll
            for (int nj = 0; nj < 8; nj++)
                m = fmaxf(m, fmaxf(accS[nj][hh * 2], accS[nj][hh * 2 + 1]));
            m = fmaxf(m, __shfl_xor_sync(0xffffffffu, m, 1));
            m = fmaxf(m, __shfl_xor_sync(0xffffffffu, m, 2));
            mx[hh] = m;
        }
        if (tg == 0) {
            #pragma unroll
            for (int hh = 0; hh < 2; hh++)
                rmax[wn * 64 + wm * 16 + hh * 8 + g] = mx[hh];
        }
        __syncthreads();

        float fsc[2], mnew[2], ls[2];
        #pragma unroll
        for (int hh = 0; hh < 2; hh++) {
            int r = wm * 16 + hh * 8 + g;
            float tm = fmaxf(rmax[r], rmax[64 + r]);
            float mn = fmaxf(m_run[hh], tm);
            mnew[hh] = mn;
            fsc[hh] = __expf(m_run[hh] - mn);
            ls[hh] = 0.f;
        }
        #pragma unroll
        for (int hh = 0; hh < 2; hh++) {
            float mn = mnew[hh];
            float s = 0.f;
            #pragma unroll
            for (int nj = 0; nj < 8; nj++) {
                float p0 = __expf(accS[nj][hh * 2] - mn);
                float p1 = __expf(accS[nj][hh * 2 + 1] - mn);
                accS[nj][hh * 2] = p0;
                accS[nj][hh * 2 + 1] = p1;
                s += p0 + p1;
            }
            ls[hh] = s;
            float f = fsc[hh];
            #pragma unroll
            for (int nj2 = 0; nj2 < 4; nj2++) {
                accO[nj2][hh * 2] *= f;
                accO[nj2][hh * 2 + 1] *= f;
            }
        }
        #pragma unroll
        for (int hh = 0; hh < 2; hh++) {
            float s = ls[hh];
            s += __shfl_xor_sync(0xffffffffu, s, 1);
            s += __shfl_xor_sync(0xffffffffu, s, 2);
            ls[hh] = s;
        }
        if (tg == 0) {
            #pragma unroll
            for (int hh = 0; hh < 2; hh++)
                rsum[wn * 64 + wm * 16 + hh * 8 + g] = ls[hh];
        }
        __syncthreads();
        #pragma unroll
        for (int hh = 0; hh < 2; hh++) {
            int r = wm * 16 + hh * 8 + g;
            l_run[hh] = l_run[hh] * fsc[hh] + rsum[r] + rsum[64 + r];
            m_run[hh] = mnew[hh];
        }

        // ---- O += P @ V (single fp16 pass) ----
        #pragma unroll
        for (int kb = 0; kb < 4; kb++) {
            uint32_t pa[4];
            pa[0] = packf16(accS[2 * kb][0], accS[2 * kb][1]);
            pa[1] = packf16(accS[2 * kb][2], accS[2 * kb][3]);
            pa[2] = packf16(accS[2 * kb + 1][0], accS[2 * kb + 1][1]);
            pa[3] = packf16(accS[2 * kb + 1][2], accS[2 * kb + 1][3]);
            uint32_t vb[4][2];
            int kcol = (wn * 64 + kb * 16 + tg * 2) * 2;
            #pragma unroll
            for (int nj2 = 0; nj2 < 4; nj2++) {
                uint32_t bh = sb + OFF_VT + (nj2 * 8 + g) * FSV + kcol;
                vb[nj2][0] = lds32(bh);
                vb[nj2][1] = lds32(bh + 16);
            }
            #pragma unroll
            for (int nj2 = 0; nj2 < 4; nj2++)
                mma_f16(accO[nj2], pa, vb[nj2]);
        }
    }

    // ---- cross-warp O reduction + normalize + fp16 store ----
    __syncthreads();
    float* Ob = (float*)smem;   // 64 x 36 floats, overlays Q/K region
    if (wn == 0) {
        #pragma unroll
        for (int hh = 0; hh < 2; hh++) {
            int r = wm * 16 + hh * 8 + g;
            #pragma unroll
            for (int nj2 = 0; nj2 < 4; nj2++) {
                Ob[r * 36 + nj2 * 8 + tg * 2]     = accO[nj2][hh * 2];
                Ob[r * 36 + nj2 * 8 + tg * 2 + 1] = accO[nj2][hh * 2 + 1];
            }
        }
    }
    __syncthreads();
    if (wn == 1) {
        #pragma unroll
        for (int hh = 0; hh < 2; hh++) {
            int r = wm * 16 + hh * 8 + g;
            float inv = 1.f / l_run[hh];
            #pragma unroll
            for (int nj2 = 0; nj2 < 4; nj2++) {
                int d = nj2 * 8 + tg * 2;
                float v0 = (Ob[r * 36 + d]     + accO[nj2][hh * 2])     * inv;
                float v1 = (Ob[r * 36 + d + 1] + accO[nj2][hh * 2 + 1]) * inv;
                long long base = (long long)(b * 1024 + q0 + r) * 256 + h * 32 + d;
                *(__half2*)&oS[base] = __floats2half2_rn(v0, v1);
            }
        }
    }
}

// ======================= depthwise conv + SiLU (fp16 in, fused fp16 outs) ==================
__global__ void __launch_bounds__(256) conv_silu_kernel(
    const __half* __restrict__ xzyh,
    const float* __restrict__ wx, const float* __restrict__ wz, const float* __restrict__ wy,
    float* __restrict__ xc, __half* __restrict__ xcS,
    __half* __restrict__ catS, __half* __restrict__ ycS)
{
    int idx = blockIdx.x * 256 + threadIdx.x;
    int d = idx & 255;
    int m = idx >> 8;
    int l = m & 1023;
    const __half* base = xzyh + (long long)m * 768;
    float a0 = 0.f, a1 = 0.f, a2 = 0.f;
    #pragma unroll
    for (int k = 0; k < 4; k++) {
        int li = l + k - 1;
        if (li < 0 || li >= 1024) continue;
        const __half* row = base + (long long)(k - 1) * 768;
        a0 = fmaf(__half2float(row[d]),       wx[d * 4 + k], a0);
        a1 = fmaf(__half2float(row[256 + d]), wz[d * 4 + k], a1);
        a2 = fmaf(__half2float(row[512 + d]), wy[d * 4 + k], a2);
    }
    a0 = a0 / (1.f + __expf(-a0));
    a1 = a1 / (1.f + __expf(-a1));
    a2 = a2 / (1.f + __expf(-a2));
    xc[idx] = a0;
    xcS[(long long)m * 256 + d] = __float2half_rn(a0);
    catS[(long long)m * 768 + 256 + d] = __float2half_rn(a1);
    ycS[(long long)m * 256 + d] = __float2half_rn(a2);
}

// ======================= selective scan (writes fp16 into catS cols [0,256)) ==============
__global__ void __launch_bounds__(256) scan_kernel(
    const float* __restrict__ delta, const float* __restrict__ xc,
    const float* __restrict__ xdbl, const float* __restrict__ A_log,
    const float* __restrict__ D_param, __half* __restrict__ catS)
{
    int t = blockIdx.x * 256 + threadIdx.x;
    int lane = t & 15;
    int p = t >> 4;
    int b = p >> 8;
    int d = p & 255;
    float Acoef = -__expf(A_log[d * 16 + lane]);
    float Dd = D_param[d];
    float h = 0.f;
    const float* dptr = delta + (long long)b * 1024 * 256 + d;
    const float* xptr = xc    + (long long)b * 1024 * 256 + d;
    const float* bptr = xdbl  + (long long)b * 1024 * 80 + 48 + lane;
    const float* cptr = bptr + 16;
    __half* optr = catS + (long long)b * 1024 * 768 + d;
    #pragma unroll 4
    for (int l = 0; l < 1024; l++) {
        float dl = dptr[(long long)l * 256];
        float xv = xptr[(long long)l * 256];
        float Bv = bptr[(long long)l * 80];
        float Cv = cptr[(long long)l * 80];
        float dA = __expf(dl * Acoef);
        h = fmaf(dA, h, dl * xv * Bv);
        float yv = h * Cv;
        yv += __shfl_xor_sync(0xffffffffu, yv, 1);
        yv += __shfl_xor_sync(0xffffffffu, yv, 2);
        yv += __shfl_xor_sync(0xffffffffu, yv, 4);
        yv += __shfl_xor_sync(0xffffffffu, yv, 8);
        if (lane == 0) {
            float v = fmaf(xv, Dd, yv);
            optr[(long long)l * 768] = __float2half_rn(v);
        }
    }
}

// ======================= host launcher =======================
extern "C" void kernel_launch(void* const* d_in, const int* in_sizes, int n_in,
                              void* d_out, int out_size)
{
    const float* hs          = (const float*)d_in[0];
    const float* in_proj_w   = (const float*)d_in[1];
    const float* conv_wx     = (const float*)d_in[2];
    const float* conv_wz     = (const float*)d_in[3];
    const float* conv_wy     = (const float*)d_in[4];
    const float* x_proj_w    = (const float*)d_in[5];
    const float* dt_proj_w   = (const float*)d_in[6];
    const float* dt_proj_b   = (const float*)d_in[7];
    const float* A_log       = (const float*)d_in[8];
    const float* D_param     = (const float*)d_in[9];
    const float* out_proj_w  = (const float*)d_in[10];
    const float* qkv_w       = (const float*)d_in[11];
    const float* attn_proj_w = (const float*)d_in[12];
    const float* attn_proj_b = (const float*)d_in[13];
    float* out = (float*)d_out;

    float *xc, *xdbl, *delta;
    cudaGetSymbolAddress((void**)&xc,    g_xc);
    cudaGetSymbolAddress((void**)&xdbl,  g_xdbl);
    cudaGetSymbolAddress((void**)&delta, g_delta);

    __half *xzyh, *qkvh, *hsS, *winS, *xcS, *wxpS, *dtS, *wdtS, *ycS, *wqkvS;
    __half *oS, *watS, *catS, *woutS;
    cudaGetSymbolAddress((void**)&xzyh,  g_xzyh);
    cudaGetSymbolAddress((void**)&qkvh,  g_qkvh);
    cudaGetSymbolAddress((void**)&hsS,   g_hsS);
    cudaGetSymbolAddress((void**)&winS,  g_winS);
    cudaGetSymbolAddress((void**)&xcS,   g_xcS);
    cudaGetSymbolAddress((void**)&wxpS,  g_wxpS);
    cudaGetSymbolAddress((void**)&dtS,   g_dtS);
    cudaGetSymbolAddress((void**)&wdtS,  g_wdtS);
    cudaGetSymbolAddress((void**)&ycS,   g_ycS);
    cudaGetSymbolAddress((void**)&wqkvS, g_wqkvS);
    cudaGetSymbolAddress((void**)&oS,    g_oS);
    cudaGetSymbolAddress((void**)&watS,  g_watS);
    cudaGetSymbolAddress((void**)&catS,  g_catS);
    cudaGetSymbolAddress((void**)&woutS, g_woutS);

    // 1) input + all-weight fp16 conversions
    half_kernel<<<12288, 256>>>(hs, 768, 4096, 768, hsS);
    weight_half_kernel<<<5760, 256>>>(in_proj_w, x_proj_w, dt_proj_w, qkv_w,
        attn_proj_w, out_proj_w, winS, wxpS, wdtS, wqkvS, watS, woutS);

    // 2) in_proj: xzyh(fp16) = hs @ in_proj_w^T   (K=768)
    gemm_mma<<<dim3(12, 32), 256>>>(hsS, winS, (float*)xzyh, 4096, 768, 768,
        768, 768, 768, 0, nullptr, 0.f, 1.f, 0, 1,
        nullptr, nullptr, nullptr, 0, 0, 0);

    // 3) depthwise conv + SiLU (fp16 in, fused fp16 outs)
    conv_silu_kernel<<<4096, 256>>>(xzyh, conv_wx, conv_wz, conv_wy, xc, xcS, catS, ycS);

    // 4) DUAL: qkv(fp16) = yc @ qkv_w^T (bx<12)  ‖  x_dbl = xc @ x_proj_w^T (bx>=12)   (K=256)
    gemm_mma<<<dim3(14, 32), 256>>>(ycS, wqkvS, (float*)qkvh, 4096, 768, 256,
        256, 256, 768, 0, nullptr, 0.f, 1.f, 0, 1,
        xcS, wxpS, xdbl, 80, 80, 12);

    // 5) fused flash attention (fp16, Q-tile 64) -> oS
    flash_kernel<<<dim3(16, 32), 256>>>(qkvh, oS);

    // 6) dt fp16 + delta = softplus(dt @ dt_proj_w^T + 2*b)   (K=48)
    half_kernel<<<768, 256>>>(xdbl, 80, 4096, 48, dtS);
    gemm_mma<<<dim3(4, 32), 256>>>(dtS, wdtS, delta, 4096, 256, 48,
        48, 48, 256, 0, dt_proj_b, 2.f, 1.f, 2, 0,
        nullptr, nullptr, nullptr, 0, 0, 0);

    // 7) selective scan -> catS cols [0,256) (fp16)
    scan_kernel<<<64, 256>>>(delta, xc, xdbl, A_log, D_param, catS);

    // 8) y_att = o @ attn_proj_w^T + b -> catS cols [512,768) (fp16 epilogue)
    gemm_mma<<<dim3(4, 32), 256>>>(oS, watS, (float*)catS, 4096, 256, 256,
        256, 256, 768, 512, attn_proj_b, 1.f, 1.f, 1, 1,
        nullptr, nullptr, nullptr, 0, 0, 0);

    // 9) out = catS @ out_proj_w^T   (K=768)
    gemm_mma<<<dim3(12, 32), 256>>>(catS, woutS, out, 4096, 768, 768,
        768, 768, 768, 0, nullptr, 0.f, 1.f, 0, 0,
        nullptr, nullptr, nullptr, 0, 0, 0);
}

// round 14
// speedup vs baseline: 1.0431x; 1.0431x over previous
#include <cuda_runtime.h>
#include <cuda_bf16.h>
#include <cuda_fp16.h>
#include <math.h>
#include <stdint.h>

// Problem constants: B=4, L=1024, DM=768, DC=256, N=16, R=48, K=4, H=8, HD=32
// GEMMs + flash attention: single-pass fp16 operands, fp32 accumulate.

// ======================= scratch buffers (static; no allocation) =======================
__device__ float g_xc[4096 * 256];
__device__ float g_xdbl[4096 * 80];
__device__ float g_delta[4096 * 256];

__device__ __half g_xzyh[4096 * 768];
__device__ __half g_qkvh[4096 * 768];
__device__ __half g_hsS[4096 * 768];
__device__ __half g_winS[768 * 768];
__device__ __half g_xcS[4096 * 256];
__device__ __half g_wxpS[80 * 256];
__device__ __half g_dtS[4096 * 48];
__device__ __half g_wdtS[256 * 48];
__device__ __half g_ycS[4096 * 256];
__device__ __half g_wqkvS[768 * 256];
__device__ __half g_oS[4096 * 256];
__device__ __half g_watS[256 * 256];
__device__ __half g_catS[4096 * 768];
__device__ __half g_woutS[768 * 768];

// ======================= small asm helpers =======================
__device__ __forceinline__ uint32_t smem_to_u32(const void* smem_ptr) {
    uint32_t addr;
    asm("{ .reg .u64 tmp; cvta.to.shared.u64 tmp, %1; cvt.u32.u64 %0, tmp; }"
        : "=r"(addr) : "l"(smem_ptr));
    return addr;
}

__device__ __forceinline__ uint32_t lds32(uint32_t a) {
    uint32_t v;
    asm volatile("ld.shared.b32 %0, [%1];" : "=r"(v) : "r"(a));
    return v;
}

__device__ __forceinline__ void ldsm4(uint32_t* r, uint32_t a) {
    asm volatile("ldmatrix.sync.aligned.m8n8.x4.shared.b16 {%0,%1,%2,%3}, [%4];"
                 : "=r"(r[0]), "=r"(r[1]), "=r"(r[2]), "=r"(r[3]) : "r"(a));
}

__device__ __forceinline__ void cp16(uint32_t dst, const void* src, bool pred) {
    int sz = pred ? 16 : 0;
    asm volatile("cp.async.cg.shared.global [%0], [%1], 16, %2;"
                 :: "r"(dst), "l"(src), "r"(sz) : "memory");
}

__device__ __forceinline__ void mma_f16(float* c, const uint32_t* a, const uint32_t* b) {
    asm volatile(
        "mma.sync.aligned.m16n8k16.row.col.f32.f16.f16.f32 "
        "{%0,%1,%2,%3}, {%4,%5,%6,%7}, {%8,%9}, {%0,%1,%2,%3};"
        : "+f"(c[0]), "+f"(c[1]), "+f"(c[2]), "+f"(c[3])
        : "r"(a[0]), "r"(a[1]), "r"(a[2]), "r"(a[3]), "r"(b[0]), "r"(b[1]));
}

__device__ __forceinline__ uint32_t packf16(float x, float y) {
    __half2 t = __floats2half2_rn(x, y);
    return *(uint32_t*)&t;
}

// ======================= fp32 -> fp16 conversion (strided) =======================
__global__ void __launch_bounds__(256) half_kernel(
    const float* __restrict__ src, int ld,
    int M, int K, __half* __restrict__ dst)
{
    int idx = blockIdx.x * 256 + threadIdx.x;
    if (idx >= M * K) return;
    int m = idx / K, k = idx - m * K;
    dst[(long long)m * K + k] = __float2half_rn(src[(long long)m * ld + k]);
}

// ======================= merged conversions: hs + all weights (contiguous) ===============
__global__ void __launch_bounds__(256) convert_all_kernel(
    const float* __restrict__ hs,
    const float* __restrict__ w_in, const float* __restrict__ w_xp,
    const float* __restrict__ w_dt, const float* __restrict__ w_qkv,
    const float* __restrict__ w_at, const float* __restrict__ w_out,
    __half* __restrict__ hsS,
    __half* __restrict__ winS, __half* __restrict__ wxpS,
    __half* __restrict__ wdtS, __half* __restrict__ wqkvS,
    __half* __restrict__ watS, __half* __restrict__ woutS)
{
    int idx = blockIdx.x * 256 + threadIdx.x;
    const float* src; __half* dst;
    int rem = idx;
    if (rem < 3145728)                { src = hs;    dst = hsS;   }
    else if ((rem -= 3145728) < 589824) { src = w_in;  dst = winS;  }
    else if ((rem -= 589824) < 20480) { src = w_xp;  dst = wxpS;  }
    else if ((rem -= 20480) < 12288)  { src = w_dt;  dst = wdtS;  }
    else if ((rem -= 12288) < 196608) { src = w_qkv; dst = wqkvS; }
    else if ((rem -= 196608) < 65536) { src = w_at;  dst = watS;  }
    else                              { rem -= 65536; src = w_out; dst = woutS; }
    dst[rem] = __float2half_rn(src[rem]);
}

// ======================= HMMA fp16 NT GEMM, 128x64x32, 3-stage + ldmatrix ====================
// epi: 0 none, 1 +bias*bscale, 2 softplus(v + bias*bscale)
// ohalf: if 1, C is a __half buffer; write fp16 at coff+c (row stride ldc elements).
// dual: if splitx>0 and blockIdx.x>=splitx, switch to full side-2 parameter set.
#define ASTR 80
#define STG 15360      // 128*80 (A) + 64*80 (B)
__global__ void __launch_bounds__(256, 3) gemm_mma(
    const __half* __restrict__ A, const __half* __restrict__ B,
    float* __restrict__ C, int M, int Nglob, int Kp,
    int lda, int ldb, int ldc, int coff,
    const float* __restrict__ bias, float bscale, float alpha, int epi,
    int ohalf,
    const __half* __restrict__ A2, const __half* __restrict__ B2,
    float* __restrict__ C2, int N2, int ldc2, int splitx,
    int Kp2, int lda2, int ldb2, int coff2,
    const float* __restrict__ bias2, float bscale2, int epi2, int ohalf2)
{
    __shared__ __align__(16) char smem[3 * STG];
    uint32_t sb = smem_to_u32(smem);
    int tid = threadIdx.x;
    int bx = blockIdx.x;
    int n0;
    if (splitx && bx >= splitx) {
        A = A2; B = B2; C = C2; Nglob = N2; ldc = ldc2;
        Kp = Kp2; lda = lda2; ldb = ldb2;
        coff = coff2; bias = bias2; bscale = bscale2; epi = epi2; ohalf = ohalf2;
        n0 = (bx - splitx) * 64;
    } else {
        n0 = bx * 64;
    }
    int m0 = blockIdx.y * 128;
    int NC = (Kp + 31) >> 5;

    auto load_stage = [&](int c) {
        int k0 = c * 32;
        uint32_t ab = sb + (c % 3) * STG;
        uint32_t bb = ab + 10240;
        #pragma unroll
        for (int i = 0; i < 2; i++) {
            int gg = tid + i * 256;
            int r = gg >> 2, c16 = gg & 3;
            int k = k0 + c16 * 8;
            cp16(ab + r * ASTR + c16 * 16, A + (long long)(m0 + r) * lda + k, k < Kp);
        }
        {
            int r = tid >> 2, c16 = tid & 3;
            int k = k0 + c16 * 8;
            cp16(bb + r * ASTR + c16 * 16, B + (long long)(n0 + r) * ldb + k,
                 (n0 + r) < Nglob && k < Kp);
        }
        asm volatile("cp.async.commit_group;" ::: "memory");
    };

    int wid = tid >> 5, lane = tid & 31;
    int wm = wid & 3, wn = wid >> 2;          // 4x2 warps, warp tile 32x32
    int g = lane >> 2, tg = lane & 3;
    int l7 = lane & 7;

    uint32_t aoff0 = (uint32_t)((wm * 32 + l7 + ((lane >> 3) & 1) * 8) * ASTR + (lane >> 4) * 16);
    uint32_t aoff1 = aoff0 + 16 * ASTR;
    uint32_t boff0 = (uint32_t)((wn * 32 + (lane >> 4) * 8 + l7) * ASTR + ((lane >> 3) & 1) * 16);
    uint32_t boff1 = boff0 + 16 * ASTR;

    float acc[2][4][4] = {};

    load_stage(0);
    if (1 < NC) load_stage(1);

    for (int c = 0; c < NC; c++) {
        if (c + 1 < NC) { asm volatile("cp.async.wait_group 1;" ::: "memory"); }
        else            { asm volatile("cp.async.wait_group 0;" ::: "memory"); }
        __syncthreads();
        if (c + 2 < NC) load_stage(c + 2);

        uint32_t ab = sb + (c % 3) * STG;
        uint32_t bb = ab + 10240;
        #pragma unroll
        for (int ks = 0; ks < 2; ks++) {
            uint32_t a0[4], a1[4], b0[4], b1[4];
            ldsm4(a0, ab + aoff0 + ks * 32);
            ldsm4(a1, ab + aoff1 + ks * 32);
            ldsm4(b0, bb + boff0 + ks * 32);
            ldsm4(b1, bb + boff1 + ks * 32);
            mma_f16(acc[0][0], a0, b0 + 0);
            mma_f16(acc[0][1], a0, b0 + 2);
            mma_f16(acc[0][2], a0, b1 + 0);
            mma_f16(acc[0][3], a0, b1 + 2);
            mma_f16(acc[1][0], a1, b0 + 0);
            mma_f16(acc[1][1], a1, b0 + 2);
            mma_f16(acc[1][2], a1, b1 + 0);
            mma_f16(acc[1][3], a1, b1 + 2);
        }
    }
    __syncthreads();

    // ---- epilogue ----
    #pragma unroll
    for (int mi = 0; mi < 2; mi++) {
        int r0 = m0 + wm * 32 + mi * 16 + g;
        #pragma unroll
        for (int nj = 0; nj < 4; nj++) {
            int cc = n0 + wn * 32 + nj * 8 + tg * 2;
            if (cc >= Nglob) continue;
            #pragma unroll
            for (int hh = 0; hh < 2; hh++) {
                int rr = r0 + hh * 8;
                float v0 = acc[mi][nj][hh * 2 + 0] * alpha;
                float v1 = acc[mi][nj][hh * 2 + 1] * alpha;
                if (epi >= 1) { v0 += bias[cc] * bscale; v1 += bias[cc + 1] * bscale; }
                if (epi == 2) {
                    v0 = (v0 > 15.f) ? v0 : log1pf(__expf(v0));
                    v1 = (v1 > 15.f) ? v1 : log1pf(__expf(v1));
                }
                if (!ohalf) {
                    *(float2*)&C[(long long)rr * ldc + coff + cc] = make_float2(v0, v1);
                } else {
                    __half* Cb = (__half*)C;
                    long long base = (long long)rr * ldc + coff + cc;
                    *(__half2*)&Cb[base] = __floats2half2_rn(v0, v1);
                }
            }
        }
    }
}

// ======================= fused flash attention, single-pass fp16, Q-tile 128 ===============
// qkvh: fp16 (4096 x 768) [q|k|v]. Q tile 128 rows, K tiles 128 keys, HD=32.
#define FQK 80                    // 32 halfs (64B) + 16 pad
#define OFF_VT 10240              // V^T: 32 x 272
#define FSV 272
#define OFF_FRMAX 18944
#define OFF_FRSUM 19968
__global__ void __launch_bounds__(256) flash_kernel(
    const __half* __restrict__ qkvh, __half* __restrict__ oS)
{
    __shared__ __align__(16) char smem[20992];
    uint32_t sb = smem_to_u32(smem);
    float* rmax = (float*)(smem + OFF_FRMAX);   // [2][128]
    float* rsum = (float*)(smem + OFF_FRSUM);   // [2][128]
    int tid = threadIdx.x;
    int wid = tid >> 5, lane = tid & 31;
    int wm = wid & 3, wn = wid >> 2;
    int g = lane >> 2, tg = lane & 3;
    int z = blockIdx.y;
    int b = z >> 3, h = z & 7;
    int q0 = blockIdx.x * 128;
    const float alpha = 0.17677669529663687f;   // HD^-0.5
    const __half* qkvb = qkvh + (long long)b * 1024 * 768 + h * 32;

    // ---- stage Q (pre-scaled) ----
    #pragma unroll
    for (int j = 0; j < 16; j++) {
        int i = tid + j * 256;
        int row = i >> 5, d = i & 31;
        float f = __half2float(qkvb[(long long)(q0 + row) * 768 + d]) * alpha;
        *(__half*)(smem + row * FQK + d * 2) = __float2half_rn(f);
    }
    __syncthreads();
    // ---- Q A-frags to registers (persistent) ----
    uint32_t qa[2][2][4];
    #pragma unroll
    for (int kb = 0; kb < 2; kb++)
        #pragma unroll
        for (int mi = 0; mi < 2; mi++) {
            uint32_t base = sb + (wm * 32 + mi * 16 + g) * FQK + kb * 32 + tg * 4;
            qa[kb][mi][0] = lds32(base);
            qa[kb][mi][1] = lds32(base + 8 * FQK);
            qa[kb][mi][2] = lds32(base + 16);
            qa[kb][mi][3] = lds32(base + 8 * FQK + 16);
        }

    float accO[2][4][4] = {};
    float m_run[2][2] = {{-1e30f, -1e30f}, {-1e30f, -1e30f}};
    float l_run[2][2] = {{0.f, 0.f}, {0.f, 0.f}};

    for (int t = 0; t < 8; t++) {
        int j0 = t * 128;
        __syncthreads();
        // ---- K tile via cp.async ----
        #pragma unroll
        for (int i = 0; i < 2; i++) {
            int gg = tid + i * 256;
            int r = gg >> 2, c16 = gg & 3;
            cp16(sb + r * FQK + c16 * 16,
                 qkvb + (long long)(j0 + r) * 768 + 256 + c16 * 8, true);
        }
        asm volatile("cp.async.commit_group;" ::: "memory");
        // ---- V^T scalar transpose copies ----
        #pragma unroll
        for (int j = 0; j < 16; j++) {
            int i = tid + j * 256;
            int key = i >> 5, d = i & 31;
            *(__half*)(smem + OFF_VT + d * FSV + key * 2) =
                qkvb[(long long)(j0 + key) * 768 + 512 + d];
        }
        asm volatile("cp.async.wait_group 0;" ::: "memory");
        __syncthreads();

        // ---- S = Q @ K^T ----
        float accS[2][8][4] = {};
        #pragma unroll
        for (int kb = 0; kb < 2; kb++) {
            uint32_t bfr[8][2];
            #pragma unroll
            for (int nj = 0; nj < 8; nj++) {
                uint32_t base = sb + (wn * 64 + nj * 8 + g) * FQK + kb * 32 + tg * 4;
                bfr[nj][0] = lds32(base);
                bfr[nj][1] = lds32(base + 16);
            }
            #pragma unroll
            for (int mi = 0; mi < 2; mi++)
                #pragma unroll
                for (int nj = 0; nj < 8; nj++)
                    mma_f16(accS[mi][nj], qa[kb][mi], bfr[nj]);
        }

        // ---- online softmax (fp32 machinery) ----
        float mx[2][2];
        #pragma unroll
        for (int mi = 0; mi < 2; mi++)
            #pragma unroll
            for (int hh = 0; hh < 2; hh++) {
                float m = -1e30f;
                #pragma unroll
                for (int nj = 0; nj < 8; nj++)
                    m = fmaxf(m, fmaxf(accS[mi][nj][hh * 2], accS[mi][nj][hh * 2 + 1]));
                m = fmaxf(m, __shfl_xor_sync(0xffffffffu, m, 1));
                m = fmaxf(m, __shfl_xor_sync(0xffffffffu, m, 2));
                mx[mi][hh] = m;
            }
        if (tg == 0) {
            #pragma unroll
            for (int mi = 0; mi < 2; mi++)
                #pragma unroll
                for (int hh = 0; hh < 2; hh++)
                    rmax[wn * 128 + wm * 32 + mi * 16 + hh * 8 + g] = mx[mi][hh];
        }
        __syncthreads();

        float fsc[2][2], mnew[2][2], ls[2][2];
        #pragma unroll
        for (int mi = 0; mi < 2; mi++)
            #pragma unroll
            for (int hh = 0; hh < 2; hh++) {
                int r = wm * 32 + mi * 16 + hh * 8 + g;
                float tm = fmaxf(rmax[r], rmax[128 + r]);
                float mn = fmaxf(m_run[mi][hh], tm);
                mnew[mi][hh] = mn;
                fsc[mi][hh] = __expf(m_run[mi][hh] - mn);
                ls[mi][hh] = 0.f;
            }
        #pragma unroll
        for (int mi = 0; mi < 2; mi++)
            #pragma unroll
            for (int hh = 0; hh < 2; hh++) {
                float mn = mnew[mi][hh];
                float s = 0.f;
                #pragma unroll
                for (int nj = 0; nj < 8; nj++) {
                    float p0 = __expf(accS[mi][nj][hh * 2] - mn);
                    float p1 = __expf(accS[mi][nj][hh * 2 + 1] - mn);
                    accS[mi][nj][hh * 2] = p0;
                    accS[mi][nj][hh * 2 + 1] = p1;
                    s += p0 + p1;
                }
                ls[mi][hh] = s;
                float f = fsc[mi][hh];
                #pragma unroll
                for (int nj2 = 0; nj2 < 4; nj2++) {
                    accO[mi][nj2][hh * 2] *= f;
                    accO[mi][nj2][hh * 2 + 1] *= f;
                }
            }
        #pragma unroll
        for (int mi = 0; mi < 2; mi++)
            #pragma unroll
            for (int hh = 0; hh < 2; hh++) {
                float s = ls[mi][hh];
                s += __shfl_xor_sync(0xffffffffu, s, 1);
                s += __shfl_xor_sync(0xffffffffu, s, 2);
                ls[mi][hh] = s;
            }
        if (tg == 0) {
            #pragma unroll
            for (int mi = 0; mi < 2; mi++)
                #pragma unroll
                for (int hh = 0; hh < 2; hh++)
                    rsum[wn * 128 + wm * 32 + mi * 16 + hh * 8 + g] = ls[mi][hh];
        }
        __syncthreads();
        #pragma unroll
        for (int mi = 0; mi < 2; mi++)
            #pragma unroll
            for (int hh = 0; hh < 2; hh++) {
                int r = wm * 32 + mi * 16 + hh * 8 + g;
                l_run[mi][hh] = l_run[mi][hh] * fsc[mi][hh] + rsum[r] + rsum[128 + r];
                m_run[mi][hh] = mnew[mi][hh];
            }

        // ---- O += P @ V  (single fp16 pass) ----
        #pragma unroll
        for (int kb = 0; kb < 4; kb++) {
            uint32_t pa[2][4];
            #pragma unroll
            for (int mi = 0; mi < 2; mi++) {
                pa[mi][0] = packf16(accS[mi][2 * kb][0], accS[mi][2 * kb][1]);
                pa[mi][1] = packf16(accS[mi][2 * kb][2], accS[mi][2 * kb][3]);
                pa[mi][2] = packf16(accS[mi][2 * kb + 1][0], accS[mi][2 * kb + 1][1]);
                pa[mi][3] = packf16(accS[mi][2 * kb + 1][2], accS[mi][2 * kb + 1][3]);
            }
            uint32_t vb[4][2];
            int kcol = (wn * 64 + kb * 16 + tg * 2) * 2;
            #pragma unroll
            for (int nj2 = 0; nj2 < 4; nj2++) {
                uint32_t bh = sb + OFF_VT + (nj2 * 8 + g) * FSV + kcol;
                vb[nj2][0] = lds32(bh);
                vb[nj2][1] = lds32(bh + 16);
            }
            #pragma unroll
            for (int mi = 0; mi < 2; mi++)
                #pragma unroll
                for (int nj2 = 0; nj2 < 4; nj2++)
                    mma_f16(accO[mi][nj2], pa[mi], vb[nj2]);
        }
    }

    // ---- cross-warp O reduction + normalize + fp16 store ----
    __syncthreads();
    float* Ob = (float*)smem;   // 128 x 36 floats
    if (wn == 0) {
        #pragma unroll
        for (int mi = 0; mi < 2; mi++)
            #pragma unroll
            for (int hh = 0; hh < 2; hh++) {
                int r = wm * 32 + mi * 16 + hh * 8 + g;
                #pragma unroll
                for (int nj2 = 0; nj2 < 4; nj2++) {
                    Ob[r * 36 + nj2 * 8 + tg * 2]     = accO[mi][nj2][hh * 2];
                    Ob[r * 36 + nj2 * 8 + tg * 2 + 1] = accO[mi][nj2][hh * 2 + 1];
                }
            }
    }
    __syncthreads();
    if (wn == 1) {
        #pragma unroll
        for (int mi = 0; mi < 2; mi++)
            #pragma unroll
            for (int hh = 0; hh < 2; hh++) {
                int r = wm * 32 + mi * 16 + hh * 8 + g;
                float inv = 1.f / l_run[mi][hh];
                #pragma unroll
                for (int nj2 = 0; nj2 < 4; nj2++) {
                    int d = nj2 * 8 + tg * 2;
                    float v0 = (Ob[r * 36 + d]     + accO[mi][nj2][hh * 2])     * inv;
                    float v1 = (Ob[r * 36 + d + 1] + accO[mi][nj2][hh * 2 + 1]) * inv;
                    long long base = (long long)(b * 1024 + q0 + r) * 256 + h * 32 + d;
                    *(__half2*)&oS[base] = __floats2half2_rn(v0, v1);
                }
            }
    }
}

// ======================= depthwise conv + SiLU (fp16 in, fused fp16 outs) ==================
__global__ void __launch_bounds__(256) conv_silu_kernel(
    const __half* __restrict__ xzyh,
    const float* __restrict__ wx, const float* __restrict__ wz, const float* __restrict__ wy,
    float* __restrict__ xc, __half* __restrict__ xcS,
    __half* __restrict__ catS, __half* __restrict__ ycS)
{
    int idx = blockIdx.x * 256 + threadIdx.x;
    int d = idx & 255;
    int m = idx >> 8;
    int l = m & 1023;
    const __half* base = xzyh + (long long)m * 768;
    float a0 = 0.f, a1 = 0.f, a2 = 0.f;
    #pragma unroll
    for (int k = 0; k < 4; k++) {
        int li = l + k - 1;
        if (li < 0 || li >= 1024) continue;
        const __half* row = base + (long long)(k - 1) * 768;
        a0 = fmaf(__half2float(row[d]),       wx[d * 4 + k], a0);
        a1 = fmaf(__half2float(row[256 + d]), wz[d * 4 + k], a1);
        a2 = fmaf(__half2float(row[512 + d]), wy[d * 4 + k], a2);
    }
    a0 = a0 / (1.f + __expf(-a0));
    a1 = a1 / (1.f + __expf(-a1));
    a2 = a2 / (1.f + __expf(-a2));
    xc[idx] = a0;
    xcS[(long long)m * 256 + d] = __float2half_rn(a0);
    catS[(long long)m * 768 + 256 + d] = __float2half_rn(a1);
    ycS[(long long)m * 256 + d] = __float2half_rn(a2);
}

// ======================= selective scan (writes fp16 into catS cols [0,256)) ==============
__global__ void __launch_bounds__(256) scan_kernel(
    const float* __restrict__ delta, const float* __restrict__ xc,
    const float* __restrict__ xdbl, const float* __restrict__ A_log,
    const float* __restrict__ D_param, __half* __restrict__ catS)
{
    int t = blockIdx.x * 256 + threadIdx.x;
    int lane = t & 15;
    int p = t >> 4;
    int b = p >> 8;
    int d = p & 255;
    float Acoef = -__expf(A_log[d * 16 + lane]);
    float Dd = D_param[d];
    float h = 0.f;
    const float* dptr = delta + (long long)b * 1024 * 256 + d;
    const float* xptr = xc    + (long long)b * 1024 * 256 + d;
    const float* bptr = xdbl  + (long long)b * 1024 * 80 + 48 + lane;
    const float* cptr = bptr + 16;
    __half* optr = catS + (long long)b * 1024 * 768 + d;
    #pragma unroll 4
    for (int l = 0; l < 1024; l++) {
        float dl = dptr[(long long)l * 256];
        float xv = xptr[(long long)l * 256];
        float Bv = bptr[(long long)l * 80];
        float Cv = cptr[(long long)l * 80];
        float dA = __expf(dl * Acoef);
        h = fmaf(dA, h, dl * xv * Bv);
        float yv = h * Cv;
        yv += __shfl_xor_sync(0xffffffffu, yv, 1);
        yv += __shfl_xor_sync(0xffffffffu, yv, 2);
        yv += __shfl_xor_sync(0xffffffffu, yv, 4);
        yv += __shfl_xor_sync(0xffffffffu, yv, 8);
        if (lane == 0) {
            float v = fmaf(xv, Dd, yv);
            optr[(long long)l * 768] = __float2half_rn(v);
        }
    }
}

// ======================= host launcher =======================
extern "C" void kernel_launch(void* const* d_in, const int* in_sizes, int n_in,
                              void* d_out, int out_size)
{
    const float* hs          = (const float*)d_in[0];
    const float* in_proj_w   = (const float*)d_in[1];
    const float* conv_wx     = (const float*)d_in[2];
    const float* conv_wz     = (const float*)d_in[3];
    const float* conv_wy     = (const float*)d_in[4];
    const float* x_proj_w    = (const float*)d_in[5];
    const float* dt_proj_w   = (const float*)d_in[6];
    const float* dt_proj_b   = (const float*)d_in[7];
    const float* A_log       = (const float*)d_in[8];
    const float* D_param     = (const float*)d_in[9];
    const float* out_proj_w  = (const float*)d_in[10];
    const float* qkv_w       = (const float*)d_in[11];
    const float* attn_proj_w = (const float*)d_in[12];
    const float* attn_proj_b = (const float*)d_in[13];
    float* out = (float*)d_out;

    float *xc, *xdbl, *delta;
    cudaGetSymbolAddress((void**)&xc,    g_xc);
    cudaGetSymbolAddress((void**)&xdbl,  g_xdbl);
    cudaGetSymbolAddress((void**)&delta, g_delta);

    __half *xzyh, *qkvh, *hsS, *winS, *xcS, *wxpS, *dtS, *wdtS, *ycS, *wqkvS;
    __half *oS, *watS, *catS, *woutS;
    cudaGetSymbolAddress((void**)&xzyh,  g_xzyh);
    cudaGetSymbolAddress((void**)&qkvh,  g_qkvh);
    cudaGetSymbolAddress((void**)&hsS,   g_hsS);
    cudaGetSymbolAddress((void**)&winS,  g_winS);
    cudaGetSymbolAddress((void**)&xcS,   g_xcS);
    cudaGetSymbolAddress((void**)&wxpS,  g_wxpS);
    cudaGetSymbolAddress((void**)&dtS,   g_dtS);
    cudaGetSymbolAddress((void**)&wdtS,  g_wdtS);
    cudaGetSymbolAddress((void**)&ycS,   g_ycS);
    cudaGetSymbolAddress((void**)&wqkvS, g_wqkvS);
    cudaGetSymbolAddress((void**)&oS,    g_oS);
    cudaGetSymbolAddress((void**)&watS,  g_watS);
    cudaGetSymbolAddress((void**)&catS,  g_catS);
    cudaGetSymbolAddress((void**)&woutS, g_woutS);

    // 1) merged conversions: hs + all weights -> fp16  (4620288 elements)
    convert_all_kernel<<<18048, 256>>>(hs, in_proj_w, x_proj_w, dt_proj_w, qkv_w,
        attn_proj_w, out_proj_w, hsS, winS, wxpS, wdtS, wqkvS, watS, woutS);

    // 2) in_proj: xzyh(fp16) = hs @ in_proj_w^T   (K=768)
    gemm_mma<<<dim3(12, 32), 256>>>(hsS, winS, (float*)xzyh, 4096, 768, 768,
        768, 768, 768, 0, nullptr, 0.f, 1.f, 0, 1,
        nullptr, nullptr, nullptr, 0, 0, 0, 0, 0, 0, 0, nullptr, 0.f, 0, 0);

    // 3) depthwise conv + SiLU (fp16 in, fused fp16 outs)
    conv_silu_kernel<<<4096, 256>>>(xzyh, conv_wx, conv_wz, conv_wy, xc, xcS, catS, ycS);

    // 4) DUAL: qkv(fp16) = yc @ qkv_w^T (bx<12)  ‖  x_dbl = xc @ x_proj_w^T (bx>=12)
    gemm_mma<<<dim3(14, 32), 256>>>(ycS, wqkvS, (float*)qkvh, 4096, 768, 256,
        256, 256, 768, 0, nullptr, 0.f, 1.f, 0, 1,
        xcS, wxpS, xdbl, 80, 80, 12, 256, 256, 256, 0, nullptr, 0.f, 0, 0);

    // 5) fused flash attention (fp16, Q-tile 128) -> oS
    flash_kernel<<<dim3(8, 32), 256>>>(qkvh, oS);

    // 6) dt fp16
    half_kernel<<<768, 256>>>(xdbl, 80, 4096, 48, dtS);

    // 7) DUAL: delta = softplus(dt @ dt_proj_w^T + 2*b) (bx<4, K=48)
    //        ‖ y_att = o @ attn_proj_w^T + b -> catS cols [512,768) (bx>=4, K=256)
    gemm_mma<<<dim3(8, 32), 256>>>(dtS, wdtS, delta, 4096, 256, 48,
        48, 48, 256, 0, dt_proj_b, 2.f, 1.f, 2, 0,
        oS, watS, (float*)catS, 256, 768, 4,
        256, 256, 256, 512, attn_proj_b, 1.f, 1, 1);

    // 8) selective scan -> catS cols [0,256) (fp16)
    scan_kernel<<<64, 256>>>(delta, xc, xdbl, A_log, D_param, catS);

    // 9) out = catS @ out_proj_w^T   (K=768)
    gemm_mma<<<dim3(12, 32), 256>>>(catS, woutS, out, 4096, 768, 768,
        768, 768, 768, 0, nullptr, 0.f, 1.f, 0, 0,
        nullptr, nullptr, nullptr, 0, 0, 0, 0, 0, 0, 0, nullptr, 0.f, 0, 0);
}

// round 16
// speedup vs baseline: 1.0503x; 1.0069x over previous
#include <cuda_runtime.h>
#include <cuda_bf16.h>
#include <cuda_fp16.h>
#include <math.h>
#include <stdint.h>

// Problem constants: B=4, L=1024, DM=768, DC=256, N=16, R=48, K=4, H=8, HD=32
// GEMMs + flash attention: single-pass fp16 operands, fp32 accumulate.

// ======================= scratch buffers (static; no allocation) =======================
__device__ float g_xc[4096 * 256];
__device__ float g_xdbl[4096 * 80];
__device__ float g_delta[4096 * 256];

__device__ __half g_xzyh[4096 * 768];
__device__ __half g_qkvh[4096 * 768];
__device__ __half g_hsS[4096 * 768];
__device__ __half g_winS[768 * 768];
__device__ __half g_xcS[4096 * 256];
__device__ __half g_wxpS[80 * 256];
__device__ __half g_dtS[4096 * 48];
__device__ __half g_wdtS[256 * 48];
__device__ __half g_ycS[4096 * 256];
__device__ __half g_wqkvS[768 * 256];
__device__ __half g_oS[4096 * 256];
__device__ __half g_watS[256 * 256];
__device__ __half g_catS[4096 * 768];
__device__ __half g_woutS[768 * 768];

// ======================= small asm helpers =======================
__device__ __forceinline__ uint32_t smem_to_u32(const void* smem_ptr) {
    uint32_t addr;
    asm("{ .reg .u64 tmp; cvta.to.shared.u64 tmp, %1; cvt.u32.u64 %0, tmp; }"
        : "=r"(addr) : "l"(smem_ptr));
    return addr;
}

__device__ __forceinline__ uint32_t lds32(uint32_t a) {
    uint32_t v;
    asm volatile("ld.shared.b32 %0, [%1];" : "=r"(v) : "r"(a));
    return v;
}

__device__ __forceinline__ void ldsm4(uint32_t* r, uint32_t a) {
    asm volatile("ldmatrix.sync.aligned.m8n8.x4.shared.b16 {%0,%1,%2,%3}, [%4];"
                 : "=r"(r[0]), "=r"(r[1]), "=r"(r[2]), "=r"(r[3]) : "r"(a));
}

__device__ __forceinline__ void cp16(uint32_t dst, const void* src, bool pred) {
    int sz = pred ? 16 : 0;
    asm volatile("cp.async.cg.shared.global [%0], [%1], 16, %2;"
                 :: "r"(dst), "l"(src), "r"(sz) : "memory");
}

__device__ __forceinline__ void mma_f16(float* c, const uint32_t* a, const uint32_t* b) {
    asm volatile(
        "mma.sync.aligned.m16n8k16.row.col.f32.f16.f16.f32 "
        "{%0,%1,%2,%3}, {%4,%5,%6,%7}, {%8,%9}, {%0,%1,%2,%3};"
        : "+f"(c[0]), "+f"(c[1]), "+f"(c[2]), "+f"(c[3])
        : "r"(a[0]), "r"(a[1]), "r"(a[2]), "r"(a[3]), "r"(b[0]), "r"(b[1]));
}

__device__ __forceinline__ uint32_t packf16(float x, float y) {
    __half2 t = __floats2half2_rn(x, y);
    return *(uint32_t*)&t;
}

// ======================= fp32 -> fp16 conversion (strided) =======================
__global__ void __launch_bounds__(256) half_kernel(
    const float* __restrict__ src, int ld,
    int M, int K, __half* __restrict__ dst)
{
    int idx = blockIdx.x * 256 + threadIdx.x;
    if (idx >= M * K) return;
    int m = idx / K, k = idx - m * K;
    dst[(long long)m * K + k] = __float2half_rn(src[(long long)m * ld + k]);
}

// ======================= merged conversions: hs + all weights (contiguous) ===============
__global__ void __launch_bounds__(256) convert_all_kernel(
    const float* __restrict__ hs,
    const float* __restrict__ w_in, const float* __restrict__ w_xp,
    const float* __restrict__ w_dt, const float* __restrict__ w_qkv,
    const float* __restrict__ w_at, const float* __restrict__ w_out,
    __half* __restrict__ hsS,
    __half* __restrict__ winS, __half* __restrict__ wxpS,
    __half* __restrict__ wdtS, __half* __restrict__ wqkvS,
    __half* __restrict__ watS, __half* __restrict__ woutS)
{
    int idx = blockIdx.x * 256 + threadIdx.x;
    const float* src; __half* dst;
    int rem = idx;
    if (rem < 3145728)                { src = hs;    dst = hsS;   }
    else if ((rem -= 3145728) < 589824) { src = w_in;  dst = winS;  }
    else if ((rem -= 589824) < 20480) { src = w_xp;  dst = wxpS;  }
    else if ((rem -= 20480) < 12288)  { src = w_dt;  dst = wdtS;  }
    else if ((rem -= 12288) < 196608) { src = w_qkv; dst = wqkvS; }
    else if ((rem -= 196608) < 65536) { src = w_at;  dst = watS;  }
    else                              { rem -= 65536; src = w_out; dst = woutS; }
    dst[rem] = __float2half_rn(src[rem]);
}

// ======================= HMMA fp16 NT GEMM, 128x64x32, 3-stage + ldmatrix ====================
// epi: 0 none, 1 +bias*bscale, 2 softplus(v + bias*bscale)
// ohalf: if 1, C is a __half buffer; write fp16 at coff+c (row stride ldc elements).
// dual: if splitx>0 and blockIdx.x>=splitx, switch to full side-2 parameter set.
#define ASTR 80
#define STG 15360      // 128*80 (A) + 64*80 (B)
__global__ void __launch_bounds__(256, 4) gemm_mma(
    const __half* __restrict__ A, const __half* __restrict__ B,
    float* __restrict__ C, int M, int Nglob, int Kp,
    int lda, int ldb, int ldc, int coff,
    const float* __restrict__ bias, float bscale, float alpha, int epi,
    int ohalf,
    const __half* __restrict__ A2, const __half* __restrict__ B2,
    float* __restrict__ C2, int N2, int ldc2, int splitx,
    int Kp2, int lda2, int ldb2, int coff2,
    const float* __restrict__ bias2, float bscale2, int epi2, int ohalf2)
{
    __shared__ __align__(16) char smem[3 * STG];
    uint32_t sb = smem_to_u32(smem);
    int tid = threadIdx.x;
    int bx = blockIdx.x;
    int n0;
    if (splitx && bx >= splitx) {
        A = A2; B = B2; C = C2; Nglob = N2; ldc = ldc2;
        Kp = Kp2; lda = lda2; ldb = ldb2;
        coff = coff2; bias = bias2; bscale = bscale2; epi = epi2; ohalf = ohalf2;
        n0 = (bx - splitx) * 64;
    } else {
        n0 = bx * 64;
    }
    int m0 = blockIdx.y * 128;
    int NC = (Kp + 31) >> 5;

    auto load_stage = [&](int c) {
        int k0 = c * 32;
        uint32_t ab = sb + (c % 3) * STG;
        uint32_t bb = ab + 10240;
        #pragma unroll
        for (int i = 0; i < 2; i++) {
            int gg = tid + i * 256;
            int r = gg >> 2, c16 = gg & 3;
            int k = k0 + c16 * 8;
            cp16(ab + r * ASTR + c16 * 16, A + (long long)(m0 + r) * lda + k, k < Kp);
        }
        {
            int r = tid >> 2, c16 = tid & 3;
            int k = k0 + c16 * 8;
            cp16(bb + r * ASTR + c16 * 16, B + (long long)(n0 + r) * ldb + k,
                 (n0 + r) < Nglob && k < Kp);
        }
        asm volatile("cp.async.commit_group;" ::: "memory");
    };

    int wid = tid >> 5, lane = tid & 31;
    int wm = wid & 3, wn = wid >> 2;          // 4x2 warps, warp tile 32x32
    int g = lane >> 2, tg = lane & 3;
    int l7 = lane & 7;

    uint32_t aoff0 = (uint32_t)((wm * 32 + l7 + ((lane >> 3) & 1) * 8) * ASTR + (lane >> 4) * 16);
    uint32_t aoff1 = aoff0 + 16 * ASTR;
    uint32_t boff0 = (uint32_t)((wn * 32 + (lane >> 4) * 8 + l7) * ASTR + ((lane >> 3) & 1) * 16);
    uint32_t boff1 = boff0 + 16 * ASTR;

    float acc[2][4][4] = {};

    load_stage(0);
    if (1 < NC) load_stage(1);

    for (int c = 0; c < NC; c++) {
        if (c + 1 < NC) { asm volatile("cp.async.wait_group 1;" ::: "memory"); }
        else            { asm volatile("cp.async.wait_group 0;" ::: "memory"); }
        __syncthreads();
        if (c + 2 < NC) load_stage(c + 2);

        uint32_t ab = sb + (c % 3) * STG;
        uint32_t bb = ab + 10240;
        #pragma unroll
        for (int ks = 0; ks < 2; ks++) {
            uint32_t a0[4], a1[4], b0[4], b1[4];
            ldsm4(a0, ab + aoff0 + ks * 32);
            ldsm4(a1, ab + aoff1 + ks * 32);
            ldsm4(b0, bb + boff0 + ks * 32);
            ldsm4(b1, bb + boff1 + ks * 32);
            mma_f16(acc[0][0], a0, b0 + 0);
            mma_f16(acc[0][1], a0, b0 + 2);
            mma_f16(acc[0][2], a0, b1 + 0);
            mma_f16(acc[0][3], a0, b1 + 2);
            mma_f16(acc[1][0], a1, b0 + 0);
            mma_f16(acc[1][1], a1, b0 + 2);
            mma_f16(acc[1][2], a1, b1 + 0);
            mma_f16(acc[1][3], a1, b1 + 2);
        }
    }
    __syncthreads();

    // ---- epilogue ----
    #pragma unroll
    for (int mi = 0; mi < 2; mi++) {
        int r0 = m0 + wm * 32 + mi * 16 + g;
        #pragma unroll
        for (int nj = 0; nj < 4; nj++) {
            int cc = n0 + wn * 32 + nj * 8 + tg * 2;
            if (cc >= Nglob) continue;
            #pragma unroll
            for (int hh = 0; hh < 2; hh++) {
                int rr = r0 + hh * 8;
                float v0 = acc[mi][nj][hh * 2 + 0] * alpha;
                float v1 = acc[mi][nj][hh * 2 + 1] * alpha;
                if (epi >= 1) { v0 += bias[cc] * bscale; v1 += bias[cc + 1] * bscale; }
                if (epi == 2) {
                    v0 = (v0 > 15.f) ? v0 : log1pf(__expf(v0));
                    v1 = (v1 > 15.f) ? v1 : log1pf(__expf(v1));
                }
                if (!ohalf) {
                    *(float2*)&C[(long long)rr * ldc + coff + cc] = make_float2(v0, v1);
                } else {
                    __half* Cb = (__half*)C;
                    long long base = (long long)rr * ldc + coff + cc;
                    *(__half2*)&Cb[base] = __floats2half2_rn(v0, v1);
                }
            }
        }
    }
}

// ======================= fused flash attention, single-pass fp16, Q-tile 128 ===============
// qkvh: fp16 (4096 x 768) [q|k|v]. Q tile 128 rows, K tiles 128 keys, HD=32.
#define FQK 80                    // 32 halfs (64B) + 16 pad
#define OFF_VT 10240              // V^T: 32 x 272
#define FSV 272
#define OFF_FRMAX 18944
#define OFF_FRSUM 19968
__global__ void __launch_bounds__(256) flash_kernel(
    const __half* __restrict__ qkvh, __half* __restrict__ oS)
{
    __shared__ __align__(16) char smem[20992];
    uint32_t sb = smem_to_u32(smem);
    float* rmax = (float*)(smem + OFF_FRMAX);   // [2][128]
    float* rsum = (float*)(smem + OFF_FRSUM);   // [2][128]
    int tid = threadIdx.x;
    int wid = tid >> 5, lane = tid & 31;
    int wm = wid & 3, wn = wid >> 2;
    int g = lane >> 2, tg = lane & 3;
    int z = blockIdx.y;
    int b = z >> 3, h = z & 7;
    int q0 = blockIdx.x * 128;
    const float alpha = 0.17677669529663687f;   // HD^-0.5
    const __half* qkvb = qkvh + (long long)b * 1024 * 768 + h * 32;

    // ---- stage Q (pre-scaled) ----
    #pragma unroll
    for (int j = 0; j < 16; j++) {
        int i = tid + j * 256;
        int row = i >> 5, d = i & 31;
        float f = __half2float(qkvb[(long long)(q0 + row) * 768 + d]) * alpha;
        *(__half*)(smem + row * FQK + d * 2) = __float2half_rn(f);
    }
    __syncthreads();
    // ---- Q A-frags to registers (persistent) ----
    uint32_t qa[2][2][4];
    #pragma unroll
    for (int kb = 0; kb < 2; kb++)
        #pragma unroll
        for (int mi = 0; mi < 2; mi++) {
            uint32_t base = sb + (wm * 32 + mi * 16 + g) * FQK + kb * 32 + tg * 4;
            qa[kb][mi][0] = lds32(base);
            qa[kb][mi][1] = lds32(base + 8 * FQK);
            qa[kb][mi][2] = lds32(base + 16);
            qa[kb][mi][3] = lds32(base + 8 * FQK + 16);
        }

    float accO[2][4][4] = {};
    float m_run[2][2] = {{-1e30f, -1e30f}, {-1e30f, -1e30f}};
    float l_run[2][2] = {{0.f, 0.f}, {0.f, 0.f}};

    for (int t = 0; t < 8; t++) {
        int j0 = t * 128;
        __syncthreads();
        // ---- K tile via cp.async ----
        #pragma unroll
        for (int i = 0; i < 2; i++) {
            int gg = tid + i * 256;
            int r = gg >> 2, c16 = gg & 3;
            cp16(sb + r * FQK + c16 * 16,
                 qkvb + (long long)(j0 + r) * 768 + 256 + c16 * 8, true);
        }
        asm volatile("cp.async.commit_group;" ::: "memory");
        // ---- V^T scalar transpose copies ----
        #pragma unroll
        for (int j = 0; j < 16; j++) {
            int i = tid + j * 256;
            int key = i >> 5, d = i & 31;
            *(__half*)(smem + OFF_VT + d * FSV + key * 2) =
                qkvb[(long long)(j0 + key) * 768 + 512 + d];
        }
        asm volatile("cp.async.wait_group 0;" ::: "memory");
        __syncthreads();

        // ---- S = Q @ K^T ----
        float accS[2][8][4] = {};
        #pragma unroll
        for (int kb = 0; kb < 2; kb++) {
            uint32_t bfr[8][2];
            #pragma unroll
            for (int nj = 0; nj < 8; nj++) {
                uint32_t base = sb + (wn * 64 + nj * 8 + g) * FQK + kb * 32 + tg * 4;
                bfr[nj][0] = lds32(base);
                bfr[nj][1] = lds32(base + 16);
            }
            #pragma unroll
            for (int mi = 0; mi < 2; mi++)
                #pragma unroll
                for (int nj = 0; nj < 8; nj++)
                    mma_f16(accS[mi][nj], qa[kb][mi], bfr[nj]);
        }

        // ---- online softmax (fp32 machinery) ----
        float mx[2][2];
        #pragma unroll
        for (int mi = 0; mi < 2; mi++)
            #pragma unroll
            for (int hh = 0; hh < 2; hh++) {
                float m = -1e30f;
                #pragma unroll
                for (int nj = 0; nj < 8; nj++)
                    m = fmaxf(m, fmaxf(accS[mi][nj][hh * 2], accS[mi][nj][hh * 2 + 1]));
                m = fmaxf(m, __shfl_xor_sync(0xffffffffu, m, 1));
                m = fmaxf(m, __shfl_xor_sync(0xffffffffu, m, 2));
                mx[mi][hh] = m;
            }
        if (tg == 0) {
            #pragma unroll
            for (int mi = 0; mi < 2; mi++)
                #pragma unroll
                for (int hh = 0; hh < 2; hh++)
                    rmax[wn * 128 + wm * 32 + mi * 16 + hh * 8 + g] = mx[mi][hh];
        }
        __syncthreads();

        float fsc[2][2], mnew[2][2], ls[2][2];
        #pragma unroll
        for (int mi = 0; mi < 2; mi++)
            #pragma unroll
            for (int hh = 0; hh < 2; hh++) {
                int r = wm * 32 + mi * 16 + hh * 8 + g;
                float tm = fmaxf(rmax[r], rmax[128 + r]);
                float mn = fmaxf(m_run[mi][hh], tm);
                mnew[mi][hh] = mn;
                fsc[mi][hh] = __expf(m_run[mi][hh] - mn);
                ls[mi][hh] = 0.f;
            }
        #pragma unroll
        for (int mi = 0; mi < 2; mi++)
            #pragma unroll
            for (int hh = 0; hh < 2; hh++) {
                float mn = mnew[mi][hh];
                float s = 0.f;
                #pragma unroll
                for (int nj = 0; nj < 8; nj++) {
                    float p0 = __expf(accS[mi][nj][hh * 2] - mn);
                    float p1 = __expf(accS[mi][nj][hh * 2 + 1] - mn);
                    accS[mi][nj][hh * 2] = p0;
                    accS[mi][nj][hh * 2 + 1] = p1;
                    s += p0 + p1;
                }
                ls[mi][hh] = s;
                float f = fsc[mi][hh];
                #pragma unroll
                for (int nj2 = 0; nj2 < 4; nj2++) {
                    accO[mi][nj2][hh * 2] *= f;
                    accO[mi][nj2][hh * 2 + 1] *= f;
                }
            }
        #pragma unroll
        for (int mi = 0; mi < 2; mi++)
            #pragma unroll
            for (int hh = 0; hh < 2; hh++) {
                float s = ls[mi][hh];
                s += __shfl_xor_sync(0xffffffffu, s, 1);
                s += __shfl_xor_sync(0xffffffffu, s, 2);
                ls[mi][hh] = s;
            }
        if (tg == 0) {
            #pragma unroll
            for (int mi = 0; mi < 2; mi++)
                #pragma unroll
                for (int hh = 0; hh < 2; hh++)
                    rsum[wn * 128 + wm * 32 + mi * 16 + hh * 8 + g] = ls[mi][hh];
        }
        __syncthreads();
        #pragma unroll
        for (int mi = 0; mi < 2; mi++)
            #pragma unroll
            for (int hh = 0; hh < 2; hh++) {
                int r = wm * 32 + mi * 16 + hh * 8 + g;
                l_run[mi][hh] = l_run[mi][hh] * fsc[mi][hh] + rsum[r] + rsum[128 + r];
                m_run[mi][hh] = mnew[mi][hh];
            }

        // ---- O += P @ V  (single fp16 pass) ----
        #pragma unroll
        for (int kb = 0; kb < 4; kb++) {
            uint32_t pa[2][4];
            #pragma unroll
            for (int mi = 0; mi < 2; mi++) {
                pa[mi][0] = packf16(accS[mi][2 * kb][0], accS[mi][2 * kb][1]);
                pa[mi][1] = packf16(accS[mi][2 * kb][2], accS[mi][2 * kb][3]);
                pa[mi][2] = packf16(accS[mi][2 * kb + 1][0], accS[mi][2 * kb + 1][1]);
                pa[mi][3] = packf16(accS[mi][2 * kb + 1][2], accS[mi][2 * kb + 1][3]);
            }
            uint32_t vb[4][2];
            int kcol = (wn * 64 + kb * 16 + tg * 2) * 2;
            #pragma unroll
            for (int nj2 = 0; nj2 < 4; nj2++) {
                uint32_t bh = sb + OFF_VT + (nj2 * 8 + g) * FSV + kcol;
                vb[nj2][0] = lds32(bh);
                vb[nj2][1] = lds32(bh + 16);
            }
            #pragma unroll
            for (int mi = 0; mi < 2; mi++)
                #pragma unroll
                for (int nj2 = 0; nj2 < 4; nj2++)
                    mma_f16(accO[mi][nj2], pa[mi], vb[nj2]);
        }
    }

    // ---- cross-warp O reduction + normalize + fp16 store ----
    __syncthreads();
    float* Ob = (float*)smem;   // 128 x 36 floats
    if (wn == 0) {
        #pragma unroll
        for (int mi = 0; mi < 2; mi++)
            #pragma unroll
            for (int hh = 0; hh < 2; hh++) {
                int r = wm * 32 + mi * 16 + hh * 8 + g;
                #pragma unroll
                for (int nj2 = 0; nj2 < 4; nj2++) {
                    Ob[r * 36 + nj2 * 8 + tg * 2]     = accO[mi][nj2][hh * 2];
                    Ob[r * 36 + nj2 * 8 + tg * 2 + 1] = accO[mi][nj2][hh * 2 + 1];
                }
            }
    }
    __syncthreads();
    if (wn == 1) {
        #pragma unroll
        for (int mi = 0; mi < 2; mi++)
            #pragma unroll
            for (int hh = 0; hh < 2; hh++) {
                int r = wm * 32 + mi * 16 + hh * 8 + g;
                float inv = 1.f / l_run[mi][hh];
                #pragma unroll
                for (int nj2 = 0; nj2 < 4; nj2++) {
                    int d = nj2 * 8 + tg * 2;
                    float v0 = (Ob[r * 36 + d]     + accO[mi][nj2][hh * 2])     * inv;
                    float v1 = (Ob[r * 36 + d + 1] + accO[mi][nj2][hh * 2 + 1]) * inv;
                    long long base = (long long)(b * 1024 + q0 + r) * 256 + h * 32 + d;
                    *(__half2*)&oS[base] = __floats2half2_rn(v0, v1);
                }
            }
    }
}

// ======================= depthwise conv + SiLU (fp16 in, fused fp16 outs) ==================
__global__ void __launch_bounds__(256) conv_silu_kernel(
    const __half* __restrict__ xzyh,
    const float* __restrict__ wx, const float* __restrict__ wz, const float* __restrict__ wy,
    float* __restrict__ xc, __half* __restrict__ xcS,
    __half* __restrict__ catS, __half* __restrict__ ycS)
{
    int idx = blockIdx.x * 256 + threadIdx.x;
    int d = idx & 255;
    int m = idx >> 8;
    int l = m & 1023;
    const __half* base = xzyh + (long long)m * 768;
    float a0 = 0.f, a1 = 0.f, a2 = 0.f;
    #pragma unroll
    for (int k = 0; k < 4; k++) {
        int li = l + k - 1;
        if (li < 0 || li >= 1024) continue;
        const __half* row = base + (long long)(k - 1) * 768;
        a0 = fmaf(__half2float(row[d]),       wx[d * 4 + k], a0);
        a1 = fmaf(__half2float(row[256 + d]), wz[d * 4 + k], a1);
        a2 = fmaf(__half2float(row[512 + d]), wy[d * 4 + k], a2);
    }
    a0 = a0 / (1.f + __expf(-a0));
    a1 = a1 / (1.f + __expf(-a1));
    a2 = a2 / (1.f + __expf(-a2));
    xc[idx] = a0;
    xcS[(long long)m * 256 + d] = __float2half_rn(a0);
    catS[(long long)m * 768 + 256 + d] = __float2half_rn(a1);
    ycS[(long long)m * 256 + d] = __float2half_rn(a2);
}

// ======================= selective scan (writes fp16 into catS cols [0,256)) ==============
__global__ void __launch_bounds__(256) scan_kernel(
    const float* __restrict__ delta, const float* __restrict__ xc,
    const float* __restrict__ xdbl, const float* __restrict__ A_log,
    const float* __restrict__ D_param, __half* __restrict__ catS)
{
    int t = blockIdx.x * 256 + threadIdx.x;
    int lane = t & 15;
    int p = t >> 4;
    int b = p >> 8;
    int d = p & 255;
    float Acoef = -__expf(A_log[d * 16 + lane]);
    float Dd = D_param[d];
    float h = 0.f;
    const float* dptr = delta + (long long)b * 1024 * 256 + d;
    const float* xptr = xc    + (long long)b * 1024 * 256 + d;
    const float* bptr = xdbl  + (long long)b * 1024 * 80 + 48 + lane;
    const float* cptr = bptr + 16;
    __half* optr = catS + (long long)b * 1024 * 768 + d;
    #pragma unroll 4
    for (int l = 0; l < 1024; l++) {
        float dl = dptr[(long long)l * 256];
        float xv = xptr[(long long)l * 256];
        float Bv = bptr[(long long)l * 80];
        float Cv = cptr[(long long)l * 80];
        float dA = __expf(dl * Acoef);
        h = fmaf(dA, h, dl * xv * Bv);
        float yv = h * Cv;
        yv += __shfl_xor_sync(0xffffffffu, yv, 1);
        yv += __shfl_xor_sync(0xffffffffu, yv, 2);
        yv += __shfl_xor_sync(0xffffffffu, yv, 4);
        yv += __shfl_xor_sync(0xffffffffu, yv, 8);
        if (lane == 0) {
            float v = fmaf(xv, Dd, yv);
            optr[(long long)l * 768] = __float2half_rn(v);
        }
    }
}

// ======================= host launcher =======================
extern "C" void kernel_launch(void* const* d_in, const int* in_sizes, int n_in,
                              void* d_out, int out_size)
{
    const float* hs          = (const float*)d_in[0];
    const float* in_proj_w   = (const float*)d_in[1];
    const float* conv_wx     = (const float*)d_in[2];
    const float* conv_wz     = (const float*)d_in[3];
    const float* conv_wy     = (const float*)d_in[4];
    const float* x_proj_w    = (const float*)d_in[5];
    const float* dt_proj_w   = (const float*)d_in[6];
    const float* dt_proj_b   = (const float*)d_in[7];
    const float* A_log       = (const float*)d_in[8];
    const float* D_param     = (const float*)d_in[9];
    const float* out_proj_w  = (const float*)d_in[10];
    const float* qkv_w       = (const float*)d_in[11];
    const float* attn_proj_w = (const float*)d_in[12];
    const float* attn_proj_b = (const float*)d_in[13];
    float* out = (float*)d_out;

    float *xc, *xdbl, *delta;
    cudaGetSymbolAddress((void**)&xc,    g_xc);
    cudaGetSymbolAddress((void**)&xdbl,  g_xdbl);
    cudaGetSymbolAddress((void**)&delta, g_delta);

    __half *xzyh, *qkvh, *hsS, *winS, *xcS, *wxpS, *dtS, *wdtS, *ycS, *wqkvS;
    __half *oS, *watS, *catS, *woutS;
    cudaGetSymbolAddress((void**)&xzyh,  g_xzyh);
    cudaGetSymbolAddress((void**)&qkvh,  g_qkvh);
    cudaGetSymbolAddress((void**)&hsS,   g_hsS);
    cudaGetSymbolAddress((void**)&winS,  g_winS);
    cudaGetSymbolAddress((void**)&xcS,   g_xcS);
    cudaGetSymbolAddress((void**)&wxpS,  g_wxpS);
    cudaGetSymbolAddress((void**)&dtS,   g_dtS);
    cudaGetSymbolAddress((void**)&wdtS,  g_wdtS);
    cudaGetSymbolAddress((void**)&ycS,   g_ycS);
    cudaGetSymbolAddress((void**)&wqkvS, g_wqkvS);
    cudaGetSymbolAddress((void**)&oS,    g_oS);
    cudaGetSymbolAddress((void**)&watS,  g_watS);
    cudaGetSymbolAddress((void**)&catS,  g_catS);
    cudaGetSymbolAddress((void**)&woutS, g_woutS);

    // 1) merged conversions: hs + all weights -> fp16
    convert_all_kernel<<<18048, 256>>>(hs, in_proj_w, x_proj_w, dt_proj_w, qkv_w,
        attn_proj_w, out_proj_w, hsS, winS, wxpS, wdtS, wqkvS, watS, woutS);

    // 2) in_proj: xzyh(fp16) = hs @ in_proj_w^T   (K=768)
    gemm_mma<<<dim3(12, 32), 256>>>(hsS, winS, (float*)xzyh, 4096, 768, 768,
        768, 768, 768, 0, nullptr, 0.f, 1.f, 0, 1,
        nullptr, nullptr, nullptr, 0, 0, 0, 0, 0, 0, 0, nullptr, 0.f, 0, 0);

    // 3) depthwise conv + SiLU (fp16 in, fused fp16 outs)
    conv_silu_kernel<<<4096, 256>>>(xzyh, conv_wx, conv_wz, conv_wy, xc, xcS, catS, ycS);

    // 4) DUAL: qkv(fp16) = yc @ qkv_w^T (bx<12)  ‖  x_dbl = xc @ x_proj_w^T (bx>=12)
    gemm_mma<<<dim3(14, 32), 256>>>(ycS, wqkvS, (float*)qkvh, 4096, 768, 256,
        256, 256, 768, 0, nullptr, 0.f, 1.f, 0, 1,
        xcS, wxpS, xdbl, 80, 80, 12, 256, 256, 256, 0, nullptr, 0.f, 0, 0);

    // 5) fused flash attention (fp16, Q-tile 128) -> oS
    flash_kernel<<<dim3(8, 32), 256>>>(qkvh, oS);

    // 6) dt fp16
    half_kernel<<<768, 256>>>(xdbl, 80, 4096, 48, dtS);

    // 7) DUAL: delta = softplus(dt @ dt_proj_w^T + 2*b) (bx<4, K=48)
    //        ‖ y_att = o @ attn_proj_w^T + b -> catS cols [512,768) (bx>=4, K=256)
    gemm_mma<<<dim3(8, 32), 256>>>(dtS, wdtS, delta, 4096, 256, 48,
        48, 48, 256, 0, dt_proj_b, 2.f, 1.f, 2, 0,
        oS, watS, (float*)catS, 256, 768, 4,
        256, 256, 256, 512, attn_proj_b, 1.f, 1, 1);

    // 8) selective scan -> catS cols [0,256) (fp16)
    scan_kernel<<<64, 256>>>(delta, xc, xdbl, A_log, D_param, catS);

    // 9) out = catS @ out_proj_w^T   (K=768)
    gemm_mma<<<dim3(12, 32), 256>>>(catS, woutS, out, 4096, 768, 768,
        768, 768, 768, 0, nullptr, 0.f, 1.f, 0, 0,
        nullptr, nullptr, nullptr, 0, 0, 0, 0, 0, 0, 0, nullptr, 0.f, 0, 0);
}